// round 1
// baseline (speedup 1.0000x reference)
#include <cuda_runtime.h>
#include <cuda_bf16.h>
#include <cstdint>

#define NN 20000
#define EE 320000
#define ET (NN + EE)      // 340000 edges incl. self loops
#define DD 128
#define HH 4
#define HD1 (HH * DD)     // 512
#define GG 256

// ---------------- scratch (static device globals; no allocs allowed) ----------
__device__ float g_h1[NN * HD1];
__device__ float g_x1[NN * HD1];
__device__ float g_h2[NN * DD];
__device__ float g_x2[NN * DD];
__device__ float g_als1[NN * HH];
__device__ float g_ald1[NN * HH];
__device__ float g_als2[NN];
__device__ float g_ald2[NN];
__device__ int   g_srcL[ET];
__device__ int   g_dstL[ET];
__device__ int   g_csrc[ET];
__device__ int   g_deg[NN];
__device__ int   g_cnt[NN];
__device__ int   g_rowptr[NN + 1];
__device__ int   g_is64;

// ---------------- helpers ----------------
__device__ __forceinline__ unsigned f2u(float f) {
    unsigned u = __float_as_uint(f);
    return (u & 0x80000000u) ? ~u : (u | 0x80000000u);
}
__device__ __forceinline__ float u2f(unsigned u) {
    return (u & 0x80000000u) ? __uint_as_float(u & 0x7fffffffu) : __uint_as_float(~u);
}
__device__ __forceinline__ float lrelu(float v) { return v > 0.f ? v : 0.2f * v; }

__device__ __forceinline__ int idx_get(const void* p, long long i) {
    if (g_is64) return (int)((const long long*)p)[i];
    return ((const int*)p)[i];
}

// ---------------- graph prep ----------------
__global__ void k_detect(const int* ei) {
    if (threadIdx.x == 0) {
        int s = 0;
        for (int i = 0; i < 200; i++) s |= ei[2 * i + 1];
        g_is64 = (s == 0) ? 1 : 0;
    }
}

__global__ void k_zero() {
    int i = blockIdx.x * blockDim.x + threadIdx.x;
    if (i < NN) { g_deg[i] = 0; g_cnt[i] = 0; }
}

__global__ void k_build(const void* ei) {
    int i = blockIdx.x * blockDim.x + threadIdx.x;
    if (i >= ET) return;
    int s, d;
    if (i < EE) {
        s = idx_get(ei, i);
        d = idx_get(ei, (long long)EE + i);
    } else {
        s = d = i - EE;   // self loops
    }
    g_srcL[i] = s;
    g_dstL[i] = d;
    atomicAdd(&g_deg[d], 1);
}

__global__ void k_scan() {   // exclusive scan of g_deg -> g_rowptr, single block 1024
    __shared__ int buf[1024];
    __shared__ int carry;
    int tid = threadIdx.x;
    if (tid == 0) { carry = 0; g_rowptr[0] = 0; }
    __syncthreads();
    for (int base = 0; base < NN; base += 1024) {
        int i = base + tid;
        int v = (i < NN) ? g_deg[i] : 0;
        buf[tid] = v;
        __syncthreads();
        for (int off = 1; off < 1024; off <<= 1) {
            int t = (tid >= off) ? buf[tid - off] : 0;
            __syncthreads();
            buf[tid] += t;
            __syncthreads();
        }
        if (i < NN) g_rowptr[i + 1] = carry + buf[tid];
        __syncthreads();
        if (tid == 0) carry += buf[1023];
        __syncthreads();
    }
}

__global__ void k_scatter() {
    int i = blockIdx.x * blockDim.x + threadIdx.x;
    if (i >= ET) return;
    int d = g_dstL[i];
    int pos = g_rowptr[d] + atomicAdd(&g_cnt[d], 1);
    g_csrc[pos] = g_srcL[i];
}

// ---------------- SGEMM 64x64x16, 256 threads, 4x4 micro-tile ----------------
__global__ void __launch_bounds__(256) k_sgemm64(const float* __restrict__ A,
                                                 const float* __restrict__ B,
                                                 float* __restrict__ C,
                                                 int M, int Nc, int K) {
    __shared__ float As[64][20];
    __shared__ float Bs[16][68];
    int tid = threadIdx.x;
    int tx = tid & 15, ty = tid >> 4;
    int rowBase = blockIdx.y * 64;
    int colBase = blockIdx.x * 64;
    int ar = tid >> 2;
    int ak = (tid & 3) * 4;
    int bk = tid >> 4;
    int bc = (tid & 15) * 4;
    float acc[4][4];
#pragma unroll
    for (int i = 0; i < 4; i++)
#pragma unroll
        for (int j = 0; j < 4; j++) acc[i][j] = 0.f;

    int arow = rowBase + ar;
    const float* Ap = A + (size_t)arow * K;
    for (int k0 = 0; k0 < K; k0 += 16) {
        float4 av = make_float4(0.f, 0.f, 0.f, 0.f);
        if (arow < M) av = *(const float4*)(Ap + k0 + ak);
        *(float4*)&As[ar][ak] = av;
        float4 bv = *(const float4*)(B + (size_t)(k0 + bk) * Nc + colBase + bc);
        *(float4*)&Bs[bk][bc] = bv;
        __syncthreads();
#pragma unroll
        for (int k = 0; k < 16; k++) {
            float a0 = As[ty * 4 + 0][k];
            float a1 = As[ty * 4 + 1][k];
            float a2 = As[ty * 4 + 2][k];
            float a3 = As[ty * 4 + 3][k];
            float4 b = *(const float4*)&Bs[k][tx * 4];
            acc[0][0] += a0 * b.x; acc[0][1] += a0 * b.y; acc[0][2] += a0 * b.z; acc[0][3] += a0 * b.w;
            acc[1][0] += a1 * b.x; acc[1][1] += a1 * b.y; acc[1][2] += a1 * b.z; acc[1][3] += a1 * b.w;
            acc[2][0] += a2 * b.x; acc[2][1] += a2 * b.y; acc[2][2] += a2 * b.z; acc[2][3] += a2 * b.w;
            acc[3][0] += a3 * b.x; acc[3][1] += a3 * b.y; acc[3][2] += a3 * b.z; acc[3][3] += a3 * b.w;
        }
        __syncthreads();
    }
#pragma unroll
    for (int i = 0; i < 4; i++) {
        int r = rowBase + ty * 4 + i;
        if (r < M)
            *(float4*)&C[(size_t)r * Nc + colBase + tx * 4] =
                make_float4(acc[i][0], acc[i][1], acc[i][2], acc[i][3]);
    }
}

// ---------------- attention-coefficient dot products ----------------
template <int H>
__global__ void k_attdot(const float* __restrict__ h,
                         const float* __restrict__ asrc,
                         const float* __restrict__ adst,
                         float* __restrict__ als, float* __restrict__ ald) {
    int n = blockIdx.x;
    int w = threadIdx.x >> 5, l = threadIdx.x & 31;
    const float* hp = h + (size_t)n * H * DD + w * DD;
    float s1 = 0.f, s2 = 0.f;
    for (int c = l; c < DD; c += 32) {
        float v = hp[c];
        s1 += v * asrc[w * DD + c];
        s2 += v * adst[w * DD + c];
    }
#pragma unroll
    for (int o = 16; o; o >>= 1) {
        s1 += __shfl_down_sync(0xffffffffu, s1, o);
        s2 += __shfl_down_sync(0xffffffffu, s2, o);
    }
    if (l == 0) { als[n * H + w] = s1; ald[n * H + w] = s2; }
}

// ---------------- GAT aggregation: one block per dst node ----------------
// mode 0: elu epilogue (layer 1). mode 1: relu epilogue (layer 2).
template <int H, int LH>
__global__ void __launch_bounds__(H * 128) k_gatagg(const float* __restrict__ hfeat,
                                                    const float* __restrict__ als,
                                                    const float* __restrict__ ald,
                                                    const float* __restrict__ bias,
                                                    float* __restrict__ out,
                                                    int mode) {
    const int HDx = H * 128;
    int d = blockIdx.x;
    int tid = threadIdx.x;
    int h = tid >> 7;
    int beg = g_rowptr[d], end = g_rowptr[d + 1];
    int deg = end - beg;

    __shared__ unsigned smax[H];
    __shared__ float sden[H];
    __shared__ float sal[64 * H];
    __shared__ int ssrc[64];
    if (tid < H) { smax[tid] = 0u; sden[tid] = 0.f; }
    __syncthreads();

    // phase 1: per-head max of leaky_relu(als[src]+ald[dst])
    for (int i = tid; i < deg * H; i += HDx) {
        int e = i >> LH, hh = i & (H - 1);
        int s = g_csrc[beg + e];
        float ev = lrelu(als[s * H + hh] + ald[d * H + hh]);
        atomicMax(&smax[hh], f2u(ev));
    }
    __syncthreads();

    // phase 2: denom
    for (int i = tid; i < deg * H; i += HDx) {
        int e = i >> LH, hh = i & (H - 1);
        int s = g_csrc[beg + e];
        float ev = lrelu(als[s * H + hh] + ald[d * H + hh]);
        atomicAdd(&sden[hh], expf(ev - u2f(smax[hh])));
    }
    __syncthreads();

    // phase 3: chunked weighted aggregation
    float acc = 0.f;
    for (int cb = beg; cb < end; cb += 64) {
        int cn = min(64, end - cb);
        if (tid < cn) ssrc[tid] = g_csrc[cb + tid];
        __syncthreads();
        for (int i = tid; i < cn * H; i += HDx) {
            int e = i >> LH, hh = i & (H - 1);
            int s = ssrc[e];
            float ev = lrelu(als[s * H + hh] + ald[d * H + hh]);
            sal[i] = expf(ev - u2f(smax[hh])) / sden[hh];
        }
        __syncthreads();
        for (int j = 0; j < cn; j++) {
            int s = ssrc[j];
            acc += sal[j * H + h] * hfeat[(size_t)s * HDx + tid];
        }
        __syncthreads();
    }

    float v = acc + bias[tid];
    v = mode ? fmaxf(v, 0.f) : (v > 0.f ? v : expm1f(v));
    out[(size_t)d * HDx + tid] = v;
}

// ---------------- fused global-max-pool + MLP ----------------
__global__ void k_pool(const void* batch, const float* __restrict__ x2,
                       const float* __restrict__ f1w, const float* __restrict__ f1b,
                       const float* __restrict__ f2w, const float* __restrict__ f2b,
                       float* __restrict__ out) {
    int g = blockIdx.x;
    int tid = threadIdx.x;  // 128
    __shared__ int slo, shi;
    if (tid == 0) {
        // lower_bound(batch, g) and lower_bound(batch, g+1) on sorted batch
        int lo = 0, hi = NN;
        while (lo < hi) { int mid = (lo + hi) >> 1; if (idx_get(batch, mid) < g) lo = mid + 1; else hi = mid; }
        slo = lo;
        lo = 0; hi = NN;
        while (lo < hi) { int mid = (lo + hi) >> 1; if (idx_get(batch, mid) < g + 1) lo = mid + 1; else hi = mid; }
        shi = lo;
    }
    __syncthreads();
    __shared__ float pr[128];
    float m = 0.f;  // x2 >= 0, and empty graphs clamp to 0 (matches reference)
    for (int n = slo; n < shi; n++) m = fmaxf(m, x2[(size_t)n * 128 + tid]);
    pr[tid] = m;
    __syncthreads();
    __shared__ float hb[16];
    if (tid < 16) {
        float s = f1b[tid];
        for (int c = 0; c < 128; c++) s += pr[c] * f1w[c * 16 + tid];
        hb[tid] = fmaxf(s, 0.f);
    }
    __syncthreads();
    if (tid == 0) {
        float s = f2b[0];
        for (int j = 0; j < 16; j++) s += hb[j] * f2w[j];
        out[g] = s;
    }
}

// ---------------- launch ----------------
extern "C" void kernel_launch(void* const* d_in, const int* in_sizes, int n_in,
                              void* d_out, int out_size) {
    const float* x   = (const float*)d_in[0];
    const void*  ei  = d_in[1];
    const void*  bat = d_in[2];
    const float* W1  = (const float*)d_in[3];
    const float* as1 = (const float*)d_in[4];
    const float* ad1 = (const float*)d_in[5];
    const float* b1  = (const float*)d_in[6];
    const float* W2  = (const float*)d_in[7];
    const float* as2 = (const float*)d_in[8];
    const float* ad2 = (const float*)d_in[9];
    const float* b2  = (const float*)d_in[10];
    const float* f1w = (const float*)d_in[11];
    const float* f1b = (const float*)d_in[12];
    const float* f2w = (const float*)d_in[13];
    const float* f2b = (const float*)d_in[14];
    float* out = (float*)d_out;

    float *p_h1, *p_x1, *p_h2, *p_x2, *p_als1, *p_ald1, *p_als2, *p_ald2;
    cudaGetSymbolAddress((void**)&p_h1, g_h1);
    cudaGetSymbolAddress((void**)&p_x1, g_x1);
    cudaGetSymbolAddress((void**)&p_h2, g_h2);
    cudaGetSymbolAddress((void**)&p_x2, g_x2);
    cudaGetSymbolAddress((void**)&p_als1, g_als1);
    cudaGetSymbolAddress((void**)&p_ald1, g_ald1);
    cudaGetSymbolAddress((void**)&p_als2, g_als2);
    cudaGetSymbolAddress((void**)&p_ald2, g_ald2);

    // graph prep
    k_detect<<<1, 32>>>((const int*)ei);
    k_zero<<<(NN + 255) / 256, 256>>>();
    k_build<<<(ET + 255) / 256, 256>>>(ei);
    k_scan<<<1, 1024>>>();
    k_scatter<<<(ET + 255) / 256, 256>>>();

    // layer 1
    {
        dim3 grid(HD1 / 64, (NN + 63) / 64);
        k_sgemm64<<<grid, 256>>>(x, W1, p_h1, NN, HD1, DD);
    }
    k_attdot<HH><<<NN, 32 * HH>>>(p_h1, as1, ad1, p_als1, p_ald1);
    k_gatagg<HH, 2><<<NN, HH * 128>>>(p_h1, p_als1, p_ald1, b1, p_x1, 0);

    // layer 2
    {
        dim3 grid(DD / 64, (NN + 63) / 64);
        k_sgemm64<<<grid, 256>>>(p_x1, W2, p_h2, NN, DD, HD1);
    }
    k_attdot<1><<<NN, 32>>>(p_h2, as2, ad2, p_als2, p_ald2);
    k_gatagg<1, 0><<<NN, 128>>>(p_h2, p_als2, p_ald2, b2, p_x2, 1);

    // pool + MLP
    k_pool<<<GG, 128>>>(bat, p_x2, f1w, f1b, f2w, f2b, out);
}

// round 2
// speedup vs baseline: 1.0234x; 1.0234x over previous
#include <cuda_runtime.h>
#include <cuda_bf16.h>
#include <cstdint>

#define NN 20000
#define EE 320000
#define ET (NN + EE)      // 340000 edges incl. self loops
#define DD 128
#define HH 4
#define HD1 (HH * DD)     // 512
#define GG 256
#define NB ((NN + 1023) / 1024)   // scan blocks (20)

// ---------------- scratch (static device globals; no allocs allowed) ----------
__device__ float g_h1[NN * HD1];
__device__ float g_x1[NN * HD1];
__device__ float g_h2[NN * DD];
__device__ float g_x2[NN * DD];
__device__ float g_als1[NN * HH];
__device__ float g_ald1[NN * HH];
__device__ float g_als2[NN];
__device__ float g_ald2[NN];
__device__ int   g_srcL[ET];
__device__ int   g_dstL[ET];
__device__ int   g_csrc[ET];
__device__ int   g_deg[NN];
__device__ int   g_cnt[NN];
__device__ int   g_rowptr[NN + 1];
__device__ int   g_bsum[32];
__device__ int   g_is64;

// ---------------- helpers ----------------
__device__ __forceinline__ float lrelu(float v) { return v > 0.f ? v : 0.2f * v; }

__device__ __forceinline__ int idx_get(const void* p, long long i) {
    if (g_is64) return (int)((const long long*)p)[i];
    return ((const int*)p)[i];
}

// ---------------- graph prep ----------------
__global__ void k_detect(const int* ei) {
    __shared__ int s;
    if (threadIdx.x == 0) s = 0;
    __syncthreads();
    int v = ei[2 * threadIdx.x + 1];   // high words if int64 (all 0), random ids if int32
    if (v) atomicOr(&s, 1);
    __syncthreads();
    if (threadIdx.x == 0) g_is64 = (s == 0) ? 1 : 0;
}

__global__ void k_zero() {
    int i = blockIdx.x * blockDim.x + threadIdx.x;
    if (i < NN) { g_deg[i] = 0; g_cnt[i] = 0; }
}

__global__ void k_build(const void* ei) {
    int i = blockIdx.x * blockDim.x + threadIdx.x;
    if (i >= ET) return;
    int s, d;
    if (i < EE) {
        s = idx_get(ei, i);
        d = idx_get(ei, (long long)EE + i);
    } else {
        s = d = i - EE;   // self loops
    }
    g_srcL[i] = s;
    g_dstL[i] = d;
    atomicAdd(&g_deg[d], 1);
}

// 3-kernel parallel exclusive scan of g_deg -> g_rowptr
__global__ void k_scan1() {   // NB blocks x 1024: per-block inclusive scan + block sums
    int b = blockIdx.x, tid = threadIdx.x;
    int i = b * 1024 + tid;
    int v = (i < NN) ? g_deg[i] : 0;
    int lane = tid & 31, w = tid >> 5;
    int x = v;
#pragma unroll
    for (int o = 1; o < 32; o <<= 1) {
        int t = __shfl_up_sync(0xffffffffu, x, o);
        if (lane >= o) x += t;
    }
    __shared__ int ws[32];
    if (lane == 31) ws[w] = x;
    __syncthreads();
    if (w == 0) {
        int y = ws[lane];
#pragma unroll
        for (int o = 1; o < 32; o <<= 1) {
            int t = __shfl_up_sync(0xffffffffu, y, o);
            if (lane >= o) y += t;
        }
        ws[lane] = y;
    }
    __syncthreads();
    int incl = x + (w ? ws[w - 1] : 0);
    if (i < NN) g_rowptr[i + 1] = incl;
    if (tid == 1023) g_bsum[b] = incl;
}

__global__ void k_scan2() {   // 1 warp: exclusive scan of block sums
    int lane = threadIdx.x;
    int v = (lane < NB) ? g_bsum[lane] : 0;
    int x = v;
#pragma unroll
    for (int o = 1; o < 32; o <<= 1) {
        int t = __shfl_up_sync(0xffffffffu, x, o);
        if (lane >= o) x += t;
    }
    if (lane < 32) g_bsum[lane] = x - v;
}

__global__ void k_scan3() {
    int i = blockIdx.x * blockDim.x + threadIdx.x;
    if (i == 0) g_rowptr[0] = 0;
    if (i < NN) g_rowptr[i + 1] += g_bsum[i >> 10];
}

__global__ void k_scatter() {
    int i = blockIdx.x * blockDim.x + threadIdx.x;
    if (i >= ET) return;
    int d = g_dstL[i];
    int pos = g_rowptr[d] + atomicAdd(&g_cnt[d], 1);
    g_csrc[pos] = g_srcL[i];
}

// ---------------- SGEMM 128x128x16, 256 threads, 8x8 micro, double-buffered ----
__global__ void __launch_bounds__(256, 2) k_sgemm128(const float* __restrict__ A,
                                                     const float* __restrict__ B,
                                                     float* __restrict__ C,
                                                     int M, int Nc, int K) {
    __shared__ float Ats[2][16][132];   // [k][row] (A transposed)
    __shared__ float Bs[2][16][132];    // [k][col]
    int tid = threadIdx.x;
    int tx = tid & 15, ty = tid >> 4;
    int rowBase = blockIdx.y * 128, colBase = blockIdx.x * 128;
    int rA = tid >> 2;            // 0..63
    int kA = (tid & 3) * 4;       // 0,4,8,12
    int rB = tid >> 4;            // 0..15
    int cB = (tid & 15) * 8;

    float acc[8][8];
#pragma unroll
    for (int i = 0; i < 8; i++)
#pragma unroll
        for (int j = 0; j < 8; j++) acc[i][j] = 0.f;

    float4 a0, a1, b0, b1;
    int r0i = rowBase + rA, r1i = rowBase + 64 + rA;
    const float* Ap0 = A + (size_t)r0i * K + kA;
    const float* Ap1 = A + (size_t)r1i * K + kA;
    const float* Bp = B + (size_t)rB * Nc + colBase + cB;

#define GLOAD(k0)                                                              \
    do {                                                                       \
        a0 = (r0i < M) ? *(const float4*)(Ap0 + (k0)) : make_float4(0, 0, 0, 0); \
        a1 = (r1i < M) ? *(const float4*)(Ap1 + (k0)) : make_float4(0, 0, 0, 0); \
        b0 = *(const float4*)(Bp + (size_t)(k0)*Nc);                           \
        b1 = *(const float4*)(Bp + (size_t)(k0)*Nc + 4);                       \
    } while (0)

#define SSTORE(buf)                                                            \
    do {                                                                       \
        Ats[buf][kA + 0][rA] = a0.x; Ats[buf][kA + 1][rA] = a0.y;              \
        Ats[buf][kA + 2][rA] = a0.z; Ats[buf][kA + 3][rA] = a0.w;              \
        Ats[buf][kA + 0][64 + rA] = a1.x; Ats[buf][kA + 1][64 + rA] = a1.y;    \
        Ats[buf][kA + 2][64 + rA] = a1.z; Ats[buf][kA + 3][64 + rA] = a1.w;    \
        *(float4*)&Bs[buf][rB][cB] = b0;                                       \
        *(float4*)&Bs[buf][rB][cB + 4] = b1;                                   \
    } while (0)

    GLOAD(0);
    SSTORE(0);
    __syncthreads();

    int KB = K / 16;
    int cur = 0;
    for (int kb = 0; kb < KB; kb++) {
        if (kb + 1 < KB) GLOAD((kb + 1) * 16);
#pragma unroll
        for (int k = 0; k < 16; k++) {
            float4 af0 = *(const float4*)&Ats[cur][k][ty * 8];
            float4 af1 = *(const float4*)&Ats[cur][k][ty * 8 + 4];
            float4 bf0 = *(const float4*)&Bs[cur][k][tx * 8];
            float4 bf1 = *(const float4*)&Bs[cur][k][tx * 8 + 4];
            float av[8] = {af0.x, af0.y, af0.z, af0.w, af1.x, af1.y, af1.z, af1.w};
            float bv[8] = {bf0.x, bf0.y, bf0.z, bf0.w, bf1.x, bf1.y, bf1.z, bf1.w};
#pragma unroll
            for (int i = 0; i < 8; i++)
#pragma unroll
                for (int j = 0; j < 8; j++) acc[i][j] += av[i] * bv[j];
        }
        if (kb + 1 < KB) {
            SSTORE(cur ^ 1);
            cur ^= 1;
            __syncthreads();
        }
    }
#undef GLOAD
#undef SSTORE

#pragma unroll
    for (int i = 0; i < 8; i++) {
        int r = rowBase + ty * 8 + i;
        if (r < M) {
            float* cp = C + (size_t)r * Nc + colBase + tx * 8;
            *(float4*)cp = make_float4(acc[i][0], acc[i][1], acc[i][2], acc[i][3]);
            *(float4*)(cp + 4) = make_float4(acc[i][4], acc[i][5], acc[i][6], acc[i][7]);
        }
    }
}

// ---------------- attention-coefficient dot products ----------------
template <int H>
__global__ void k_attdot(const float* __restrict__ h,
                         const float* __restrict__ asrc,
                         const float* __restrict__ adst,
                         float* __restrict__ als, float* __restrict__ ald) {
    int n = blockIdx.x;
    int w = threadIdx.x >> 5, l = threadIdx.x & 31;
    const float* hp = h + (size_t)n * H * DD + w * DD;
    float s1 = 0.f, s2 = 0.f;
    for (int c = l; c < DD; c += 32) {
        float v = hp[c];
        s1 += v * asrc[w * DD + c];
        s2 += v * adst[w * DD + c];
    }
#pragma unroll
    for (int o = 16; o; o >>= 1) {
        s1 += __shfl_down_sync(0xffffffffu, s1, o);
        s2 += __shfl_down_sync(0xffffffffu, s2, o);
    }
    if (l == 0) { als[n * H + w] = s1; ald[n * H + w] = s2; }
}

// ---------------- GAT aggregation: one block per dst node ----------------
// Softmax computed WITHOUT max-subtraction (mathematically identical; logits ~ +-3).
// mode 0: elu epilogue (layer 1). mode 1: relu epilogue (layer 2).
template <int H, int LH>
__global__ void __launch_bounds__(H * 128) k_gatagg(const float* __restrict__ hfeat,
                                                    const float* __restrict__ als,
                                                    const float* __restrict__ ald,
                                                    const float* __restrict__ bias,
                                                    float* __restrict__ out,
                                                    int mode) {
    const int HDx = H * 128;
    int d = blockIdx.x;
    int tid = threadIdx.x;
    int h = tid >> 7;
    int beg = g_rowptr[d], end = g_rowptr[d + 1];
    int deg = end - beg;

    __shared__ float sden[H], sinv[H], sald[H];
    __shared__ float sal[64 * H];
    __shared__ int ssrc[64];
    if (tid < H) { sden[tid] = 0.f; sald[tid] = ald[d * H + tid]; }
    __syncthreads();

    // phase 1: denom = sum exp(leaky_relu(als[src]+ald[dst]))
    for (int i = tid; i < deg * H; i += HDx) {
        int e = i >> LH, hh = i & (H - 1);
        int s = g_csrc[beg + e];
        float ev = lrelu(als[s * H + hh] + sald[hh]);
        atomicAdd(&sden[hh], __expf(ev));
    }
    __syncthreads();
    if (tid < H) sinv[tid] = 1.f / sden[tid];
    __syncthreads();

    // phase 2: chunked weighted aggregation
    float acc0 = 0.f, acc1 = 0.f;
    for (int cb = beg; cb < end; cb += 64) {
        int cn = min(64, end - cb);
        if (tid < cn) ssrc[tid] = g_csrc[cb + tid];
        __syncthreads();
        for (int i = tid; i < cn * H; i += HDx) {
            int e = i >> LH, hh = i & (H - 1);
            float ev = lrelu(als[ssrc[e] * H + hh] + sald[hh]);
            sal[i] = __expf(ev) * sinv[hh];
        }
        __syncthreads();
        int j = 0;
        for (; j + 4 <= cn; j += 4) {
            const float* r0 = hfeat + (size_t)ssrc[j + 0] * HDx;
            const float* r1 = hfeat + (size_t)ssrc[j + 1] * HDx;
            const float* r2 = hfeat + (size_t)ssrc[j + 2] * HDx;
            const float* r3 = hfeat + (size_t)ssrc[j + 3] * HDx;
            float p0 = sal[(j + 0) * H + h];
            float p1 = sal[(j + 1) * H + h];
            float p2 = sal[(j + 2) * H + h];
            float p3 = sal[(j + 3) * H + h];
            acc0 += p0 * r0[tid];
            acc1 += p1 * r1[tid];
            acc0 += p2 * r2[tid];
            acc1 += p3 * r3[tid];
        }
        for (; j < cn; j++)
            acc0 += sal[j * H + h] * hfeat[(size_t)ssrc[j] * HDx + tid];
        __syncthreads();
    }

    float v = acc0 + acc1 + bias[tid];
    v = mode ? fmaxf(v, 0.f) : (v > 0.f ? v : expm1f(v));
    out[(size_t)d * HDx + tid] = v;
}

// ---------------- fused global-max-pool + MLP ----------------
__global__ void k_pool(const void* batch, const float* __restrict__ x2,
                       const float* __restrict__ f1w, const float* __restrict__ f1b,
                       const float* __restrict__ f2w, const float* __restrict__ f2b,
                       float* __restrict__ out) {
    int g = blockIdx.x;
    int tid = threadIdx.x;  // 128
    __shared__ int slo, shi;
    if (tid == 0) {
        int lo = 0, hi = NN;
        while (lo < hi) { int mid = (lo + hi) >> 1; if (idx_get(batch, mid) < g) lo = mid + 1; else hi = mid; }
        slo = lo;
        lo = 0; hi = NN;
        while (lo < hi) { int mid = (lo + hi) >> 1; if (idx_get(batch, mid) < g + 1) lo = mid + 1; else hi = mid; }
        shi = lo;
    }
    __syncthreads();
    __shared__ float pr[128];
    float m = 0.f;  // x2 >= 0; empty graphs clamp to 0 (matches reference)
    for (int n = slo; n < shi; n++) m = fmaxf(m, x2[(size_t)n * 128 + tid]);
    pr[tid] = m;
    __syncthreads();
    __shared__ float hb[16];
    if (tid < 16) {
        float s = f1b[tid];
        for (int c = 0; c < 128; c++) s += pr[c] * f1w[c * 16 + tid];
        hb[tid] = fmaxf(s, 0.f);
    }
    __syncthreads();
    if (tid == 0) {
        float s = f2b[0];
        for (int j = 0; j < 16; j++) s += hb[j] * f2w[j];
        out[g] = s;
    }
}

// ---------------- launch ----------------
extern "C" void kernel_launch(void* const* d_in, const int* in_sizes, int n_in,
                              void* d_out, int out_size) {
    const float* x   = (const float*)d_in[0];
    const void*  ei  = d_in[1];
    const void*  bat = d_in[2];
    const float* W1  = (const float*)d_in[3];
    const float* as1 = (const float*)d_in[4];
    const float* ad1 = (const float*)d_in[5];
    const float* b1  = (const float*)d_in[6];
    const float* W2  = (const float*)d_in[7];
    const float* as2 = (const float*)d_in[8];
    const float* ad2 = (const float*)d_in[9];
    const float* b2  = (const float*)d_in[10];
    const float* f1w = (const float*)d_in[11];
    const float* f1b = (const float*)d_in[12];
    const float* f2w = (const float*)d_in[13];
    const float* f2b = (const float*)d_in[14];
    float* out = (float*)d_out;

    float *p_h1, *p_x1, *p_h2, *p_x2, *p_als1, *p_ald1, *p_als2, *p_ald2;
    cudaGetSymbolAddress((void**)&p_h1, g_h1);
    cudaGetSymbolAddress((void**)&p_x1, g_x1);
    cudaGetSymbolAddress((void**)&p_h2, g_h2);
    cudaGetSymbolAddress((void**)&p_x2, g_x2);
    cudaGetSymbolAddress((void**)&p_als1, g_als1);
    cudaGetSymbolAddress((void**)&p_ald1, g_ald1);
    cudaGetSymbolAddress((void**)&p_als2, g_als2);
    cudaGetSymbolAddress((void**)&p_ald2, g_ald2);

    // graph prep
    k_detect<<<1, 64>>>((const int*)ei);
    k_zero<<<(NN + 255) / 256, 256>>>();
    k_build<<<(ET + 255) / 256, 256>>>(ei);
    k_scan1<<<NB, 1024>>>();
    k_scan2<<<1, 32>>>();
    k_scan3<<<(NN + 255) / 256, 256>>>();
    k_scatter<<<(ET + 255) / 256, 256>>>();

    // layer 1
    {
        dim3 grid(HD1 / 128, (NN + 127) / 128);
        k_sgemm128<<<grid, 256>>>(x, W1, p_h1, NN, HD1, DD);
    }
    k_attdot<HH><<<NN, 32 * HH>>>(p_h1, as1, ad1, p_als1, p_ald1);
    k_gatagg<HH, 2><<<NN, HH * 128>>>(p_h1, p_als1, p_ald1, b1, p_x1, 0);

    // layer 2
    {
        dim3 grid(DD / 128, (NN + 127) / 128);
        k_sgemm128<<<grid, 256>>>(p_x1, W2, p_h2, NN, DD, HD1);
    }
    k_attdot<1><<<NN, 32>>>(p_h2, as2, ad2, p_als2, p_ald2);
    k_gatagg<1, 0><<<NN, 128>>>(p_h2, p_als2, p_ald2, b2, p_x2, 1);

    // pool + MLP
    k_pool<<<GG, 128>>>(bat, p_x2, f1w, f1b, f2w, f2b, out);
}

// round 3
// speedup vs baseline: 1.3622x; 1.3311x over previous
#include <cuda_runtime.h>
#include <cuda_bf16.h>
#include <cstdint>

#define NN 20000
#define EE 320000
#define ET (NN + EE)      // 340000 edges incl. self loops
#define DD 128
#define HH 4
#define HD1 (HH * DD)     // 512
#define GG 256
#define NB ((NN + 1023) / 1024)   // scan blocks (20)

typedef __nv_bfloat16 bf16;

// ---------------- scratch (static device globals; no allocs allowed) ----------
__device__ float g_h1[NN * HD1];
__device__ float g_h2[NN * DD];
__device__ float g_x2[NN * DD];
__device__ bf16  g_xh[NN * DD];
__device__ bf16  g_xl[NN * DD];
__device__ bf16  g_x1h[NN * HD1];
__device__ bf16  g_x1l[NN * HD1];
__device__ bf16  g_w1h[DD * HD1];
__device__ bf16  g_w1l[DD * HD1];
__device__ bf16  g_w2h[HD1 * DD];
__device__ bf16  g_w2l[HD1 * DD];
__device__ float g_als1[NN * HH];
__device__ float g_ald1[NN * HH];
__device__ float g_als2[NN];
__device__ float g_ald2[NN];
__device__ int   g_srcL[ET];
__device__ int   g_dstL[ET];
__device__ int   g_csrc[ET];
__device__ int   g_deg[NN];
__device__ int   g_cnt[NN];
__device__ int   g_rowptr[NN + 1];
__device__ int   g_bsum[32];
__device__ int   g_is64;

// ---------------- helpers ----------------
__device__ __forceinline__ float lrelu(float v) { return v > 0.f ? v : 0.2f * v; }

__device__ __forceinline__ int idx_get(const void* p, long long i) {
    if (g_is64) return (int)((const long long*)p)[i];
    return ((const int*)p)[i];
}

__device__ __forceinline__ void mma_bf16(float* c, const uint32_t* a, const uint32_t* b) {
    asm volatile(
        "mma.sync.aligned.m16n8k16.row.col.f32.bf16.bf16.f32 "
        "{%0,%1,%2,%3}, {%4,%5,%6,%7}, {%8,%9}, {%0,%1,%2,%3};\n"
        : "+f"(c[0]), "+f"(c[1]), "+f"(c[2]), "+f"(c[3])
        : "r"(a[0]), "r"(a[1]), "r"(a[2]), "r"(a[3]), "r"(b[0]), "r"(b[1]));
}
__device__ __forceinline__ void ldsm_x4(uint32_t* r, uint32_t addr) {
    asm volatile("ldmatrix.sync.aligned.m8n8.x4.shared.b16 {%0,%1,%2,%3}, [%4];"
                 : "=r"(r[0]), "=r"(r[1]), "=r"(r[2]), "=r"(r[3]) : "r"(addr));
}
__device__ __forceinline__ void ldsm_x4_t(uint32_t* r, uint32_t addr) {
    asm volatile("ldmatrix.sync.aligned.m8n8.x4.trans.shared.b16 {%0,%1,%2,%3}, [%4];"
                 : "=r"(r[0]), "=r"(r[1]), "=r"(r[2]), "=r"(r[3]) : "r"(addr));
}

// ---------------- fp32 -> split bf16 ----------------
__global__ void k_split(const float* __restrict__ in, bf16* __restrict__ hi,
                        bf16* __restrict__ lo, int n) {
    int i = blockIdx.x * blockDim.x + threadIdx.x;
    if (i >= n) return;
    float v = in[i];
    bf16 h = __float2bfloat16(v);
    hi[i] = h;
    lo[i] = __float2bfloat16(v - __bfloat162float(h));
}

// ---------------- graph prep ----------------
__global__ void k_detect(const int* ei) {
    __shared__ int s;
    if (threadIdx.x == 0) s = 0;
    __syncthreads();
    int v = ei[2 * threadIdx.x + 1];   // high words if int64 (all 0), random ids if int32
    if (v) atomicOr(&s, 1);
    __syncthreads();
    if (threadIdx.x == 0) g_is64 = (s == 0) ? 1 : 0;
}

__global__ void k_zero() {
    int i = blockIdx.x * blockDim.x + threadIdx.x;
    if (i < NN) { g_deg[i] = 0; g_cnt[i] = 0; }
}

__global__ void k_build(const void* ei) {
    int i = blockIdx.x * blockDim.x + threadIdx.x;
    if (i >= ET) return;
    int s, d;
    if (i < EE) {
        s = idx_get(ei, i);
        d = idx_get(ei, (long long)EE + i);
    } else {
        s = d = i - EE;   // self loops
    }
    g_srcL[i] = s;
    g_dstL[i] = d;
    atomicAdd(&g_deg[d], 1);
}

// 3-kernel parallel exclusive scan of g_deg -> g_rowptr
__global__ void k_scan1() {
    int b = blockIdx.x, tid = threadIdx.x;
    int i = b * 1024 + tid;
    int v = (i < NN) ? g_deg[i] : 0;
    int lane = tid & 31, w = tid >> 5;
    int x = v;
#pragma unroll
    for (int o = 1; o < 32; o <<= 1) {
        int t = __shfl_up_sync(0xffffffffu, x, o);
        if (lane >= o) x += t;
    }
    __shared__ int ws[32];
    if (lane == 31) ws[w] = x;
    __syncthreads();
    if (w == 0) {
        int y = ws[lane];
#pragma unroll
        for (int o = 1; o < 32; o <<= 1) {
            int t = __shfl_up_sync(0xffffffffu, y, o);
            if (lane >= o) y += t;
        }
        ws[lane] = y;
    }
    __syncthreads();
    int incl = x + (w ? ws[w - 1] : 0);
    if (i < NN) g_rowptr[i + 1] = incl;
    if (tid == 1023) g_bsum[b] = incl;
}

__global__ void k_scan2() {
    int lane = threadIdx.x;
    int v = (lane < NB) ? g_bsum[lane] : 0;
    int x = v;
#pragma unroll
    for (int o = 1; o < 32; o <<= 1) {
        int t = __shfl_up_sync(0xffffffffu, x, o);
        if (lane >= o) x += t;
    }
    if (lane < 32) g_bsum[lane] = x - v;
}

__global__ void k_scan3() {
    int i = blockIdx.x * blockDim.x + threadIdx.x;
    if (i == 0) g_rowptr[0] = 0;
    if (i < NN) g_rowptr[i + 1] += g_bsum[i >> 10];
}

__global__ void k_scatter() {
    int i = blockIdx.x * blockDim.x + threadIdx.x;
    if (i >= ET) return;
    int d = g_dstL[i];
    int pos = g_rowptr[d] + atomicAdd(&g_cnt[d], 1);
    g_csrc[pos] = g_srcL[i];
}

// ---------------- split-bf16 tensor-core GEMM: C = A@B (fp32 out) ------------
// Tile 128x128xK, 256 threads (8 warps as 2x4), warp tile 64x32, mma m16n8k16.
// C = Ah@Bh + Ah@Bl + Al@Bh  (~fp32 accuracy). A row-major [M,K], B row-major [K,N].
#define ASTR 24     // smem row stride (bf16) for A tile: conflict-free ldmatrix
#define BSTR 136    // smem row stride (bf16) for B tile

__global__ void __launch_bounds__(256, 2) k_mmagemm(
    const bf16* __restrict__ Ah, const bf16* __restrict__ Al,
    const bf16* __restrict__ Bh, const bf16* __restrict__ Bl,
    float* __restrict__ C, int M, int Nc, int K) {
    __shared__ bf16 sA[2][2][128 * ASTR];
    __shared__ bf16 sB[2][2][16 * BSTR];
    int tid = threadIdx.x;
    int lane = tid & 31, w = tid >> 5;
    int warpM = (w >> 2) * 64, warpN = (w & 3) * 32;
    int rowBase = blockIdx.y * 128, colBase = blockIdx.x * 128;

    float acc[4][4][4];
#pragma unroll
    for (int a = 0; a < 4; a++)
#pragma unroll
        for (int b = 0; b < 4; b++)
#pragma unroll
            for (int c = 0; c < 4; c++) acc[a][b][c] = 0.f;

    // global load indexing
    int arow = rowBase + (tid >> 1);
    int akoff = (tid & 1) * 8;
    int brow = tid >> 4;
    int bcoff = (tid & 15) * 8;
    const uint4 z4 = make_uint4(0, 0, 0, 0);
    uint4 rah, ral, rbh, rbl;

#define GLOAD(k0)                                                                   \
    do {                                                                            \
        rah = (arow < M) ? *(const uint4*)&Ah[(size_t)arow * K + (k0) + akoff] : z4;\
        ral = (arow < M) ? *(const uint4*)&Al[(size_t)arow * K + (k0) + akoff] : z4;\
        rbh = *(const uint4*)&Bh[(size_t)((k0) + brow) * Nc + colBase + bcoff];     \
        rbl = *(const uint4*)&Bl[(size_t)((k0) + brow) * Nc + colBase + bcoff];     \
    } while (0)

#define SSTORE(st)                                                                  \
    do {                                                                            \
        *(uint4*)&sA[st][0][(tid >> 1) * ASTR + akoff] = rah;                       \
        *(uint4*)&sA[st][1][(tid >> 1) * ASTR + akoff] = ral;                       \
        *(uint4*)&sB[st][0][brow * BSTR + bcoff] = rbh;                             \
        *(uint4*)&sB[st][1][brow * BSTR + bcoff] = rbl;                             \
    } while (0)

    GLOAD(0);
    SSTORE(0);
    __syncthreads();

    int KB = K / 16;
    int st = 0;
    for (int kb = 0; kb < KB; kb++) {
        if (kb + 1 < KB) GLOAD((kb + 1) * 16);

        // B fragments for this warp's 4 n-tiles (hi & lo)
        uint32_t bh[4][2], bl[4][2];
#pragma unroll
        for (int g = 0; g < 2; g++) {
            uint32_t q[4];
            uint32_t addr = (uint32_t)__cvta_generic_to_shared(
                &sB[st][0][(lane & 15) * BSTR + warpN + g * 16 + (lane >> 4) * 8]);
            ldsm_x4_t(q, addr);
            bh[2 * g][0] = q[0]; bh[2 * g][1] = q[1];
            bh[2 * g + 1][0] = q[2]; bh[2 * g + 1][1] = q[3];
            addr = (uint32_t)__cvta_generic_to_shared(
                &sB[st][1][(lane & 15) * BSTR + warpN + g * 16 + (lane >> 4) * 8]);
            ldsm_x4_t(q, addr);
            bl[2 * g][0] = q[0]; bl[2 * g][1] = q[1];
            bl[2 * g + 1][0] = q[2]; bl[2 * g + 1][1] = q[3];
        }
#pragma unroll
        for (int mt = 0; mt < 4; mt++) {
            uint32_t ah[4], al[4];
            uint32_t addr = (uint32_t)__cvta_generic_to_shared(
                &sA[st][0][(warpM + mt * 16 + (lane & 15)) * ASTR + (lane >> 4) * 8]);
            ldsm_x4(ah, addr);
            addr = (uint32_t)__cvta_generic_to_shared(
                &sA[st][1][(warpM + mt * 16 + (lane & 15)) * ASTR + (lane >> 4) * 8]);
            ldsm_x4(al, addr);
#pragma unroll
            for (int nt = 0; nt < 4; nt++) {
                mma_bf16(acc[mt][nt], ah, bh[nt]);
                mma_bf16(acc[mt][nt], ah, bl[nt]);
                mma_bf16(acc[mt][nt], al, bh[nt]);
            }
        }
        if (kb + 1 < KB) {
            SSTORE(st ^ 1);
            st ^= 1;
            __syncthreads();
        }
    }
#undef GLOAD
#undef SSTORE

    // epilogue: fp32 direct to global
    int row0 = lane >> 2, col0 = (lane & 3) * 2;
#pragma unroll
    for (int mt = 0; mt < 4; mt++) {
        int r0 = rowBase + warpM + mt * 16 + row0;
#pragma unroll
        for (int nt = 0; nt < 4; nt++) {
            int cix = colBase + warpN + nt * 8 + col0;
            if (r0 < M)
                *(float2*)&C[(size_t)r0 * Nc + cix] = make_float2(acc[mt][nt][0], acc[mt][nt][1]);
            if (r0 + 8 < M)
                *(float2*)&C[(size_t)(r0 + 8) * Nc + cix] = make_float2(acc[mt][nt][2], acc[mt][nt][3]);
        }
    }
}

// ---------------- attention-coefficient dot products ----------------
template <int H>
__global__ void k_attdot(const float* __restrict__ h,
                         const float* __restrict__ asrc,
                         const float* __restrict__ adst,
                         float* __restrict__ als, float* __restrict__ ald) {
    int n = blockIdx.x;
    int w = threadIdx.x >> 5, l = threadIdx.x & 31;
    const float* hp = h + (size_t)n * H * DD + w * DD;
    float s1 = 0.f, s2 = 0.f;
    for (int c = l; c < DD; c += 32) {
        float v = hp[c];
        s1 += v * asrc[w * DD + c];
        s2 += v * adst[w * DD + c];
    }
#pragma unroll
    for (int o = 16; o; o >>= 1) {
        s1 += __shfl_down_sync(0xffffffffu, s1, o);
        s2 += __shfl_down_sync(0xffffffffu, s2, o);
    }
    if (l == 0) { als[n * H + w] = s1; ald[n * H + w] = s2; }
}

// ---------------- GAT aggregation: one block per dst node ----------------
// Softmax without max-subtraction (mathematically identical; logits are tiny).
// MODE 0: elu epilogue, writes split-bf16 (layer 1). MODE 1: relu, fp32 out (layer 2).
template <int H, int LH, int MODE>
__global__ void __launch_bounds__(H * 128) k_gatagg(const float* __restrict__ hfeat,
                                                    const float* __restrict__ als,
                                                    const float* __restrict__ ald,
                                                    const float* __restrict__ bias,
                                                    float* __restrict__ outf,
                                                    bf16* __restrict__ outh,
                                                    bf16* __restrict__ outl) {
    const int HDx = H * 128;
    int d = blockIdx.x;
    int tid = threadIdx.x;
    int h = tid >> 7;
    int beg = g_rowptr[d], end = g_rowptr[d + 1];
    int deg = end - beg;

    __shared__ float sden[H], sinv[H], sald[H];
    __shared__ float sal[64 * H];
    __shared__ int ssrc[64];
    if (tid < H) { sden[tid] = 0.f; sald[tid] = ald[d * H + tid]; }
    __syncthreads();

    for (int i = tid; i < deg * H; i += HDx) {
        int e = i >> LH, hh = i & (H - 1);
        int s = g_csrc[beg + e];
        float ev = lrelu(als[s * H + hh] + sald[hh]);
        atomicAdd(&sden[hh], __expf(ev));
    }
    __syncthreads();
    if (tid < H) sinv[tid] = 1.f / sden[tid];
    __syncthreads();

    float acc0 = 0.f, acc1 = 0.f;
    for (int cb = beg; cb < end; cb += 64) {
        int cn = min(64, end - cb);
        if (tid < cn) ssrc[tid] = g_csrc[cb + tid];
        __syncthreads();
        for (int i = tid; i < cn * H; i += HDx) {
            int e = i >> LH, hh = i & (H - 1);
            float ev = lrelu(als[ssrc[e] * H + hh] + sald[hh]);
            sal[i] = __expf(ev) * sinv[hh];
        }
        __syncthreads();
        int j = 0;
        for (; j + 4 <= cn; j += 4) {
            const float* r0 = hfeat + (size_t)ssrc[j + 0] * HDx;
            const float* r1 = hfeat + (size_t)ssrc[j + 1] * HDx;
            const float* r2 = hfeat + (size_t)ssrc[j + 2] * HDx;
            const float* r3 = hfeat + (size_t)ssrc[j + 3] * HDx;
            float p0 = sal[(j + 0) * H + h];
            float p1 = sal[(j + 1) * H + h];
            float p2 = sal[(j + 2) * H + h];
            float p3 = sal[(j + 3) * H + h];
            acc0 += p0 * r0[tid];
            acc1 += p1 * r1[tid];
            acc0 += p2 * r2[tid];
            acc1 += p3 * r3[tid];
        }
        for (; j < cn; j++)
            acc0 += sal[j * H + h] * hfeat[(size_t)ssrc[j] * HDx + tid];
        __syncthreads();
    }

    float v = acc0 + acc1 + bias[tid];
    if (MODE == 1) {
        outf[(size_t)d * HDx + tid] = fmaxf(v, 0.f);
    } else {
        v = v > 0.f ? v : expm1f(v);
        bf16 hi = __float2bfloat16(v);
        outh[(size_t)d * HDx + tid] = hi;
        outl[(size_t)d * HDx + tid] = __float2bfloat16(v - __bfloat162float(hi));
    }
}

// ---------------- fused global-max-pool + MLP ----------------
__global__ void k_pool(const void* batch, const float* __restrict__ x2,
                       const float* __restrict__ f1w, const float* __restrict__ f1b,
                       const float* __restrict__ f2w, const float* __restrict__ f2b,
                       float* __restrict__ out) {
    int g = blockIdx.x;
    int tid = threadIdx.x;  // 128
    __shared__ int slo, shi;
    if (tid == 0) {
        int lo = 0, hi = NN;
        while (lo < hi) { int mid = (lo + hi) >> 1; if (idx_get(batch, mid) < g) lo = mid + 1; else hi = mid; }
        slo = lo;
        lo = 0; hi = NN;
        while (lo < hi) { int mid = (lo + hi) >> 1; if (idx_get(batch, mid) < g + 1) lo = mid + 1; else hi = mid; }
        shi = lo;
    }
    __syncthreads();
    __shared__ float pr[128];
    float m = 0.f;
    for (int n = slo; n < shi; n++) m = fmaxf(m, x2[(size_t)n * 128 + tid]);
    pr[tid] = m;
    __syncthreads();
    __shared__ float hb[16];
    if (tid < 16) {
        float s = f1b[tid];
        for (int c = 0; c < 128; c++) s += pr[c] * f1w[c * 16 + tid];
        hb[tid] = fmaxf(s, 0.f);
    }
    __syncthreads();
    if (tid == 0) {
        float s = f2b[0];
        for (int j = 0; j < 16; j++) s += hb[j] * f2w[j];
        out[g] = s;
    }
}

// ---------------- launch ----------------
extern "C" void kernel_launch(void* const* d_in, const int* in_sizes, int n_in,
                              void* d_out, int out_size) {
    const float* x   = (const float*)d_in[0];
    const void*  ei  = d_in[1];
    const void*  bat = d_in[2];
    const float* W1  = (const float*)d_in[3];
    const float* as1 = (const float*)d_in[4];
    const float* ad1 = (const float*)d_in[5];
    const float* b1  = (const float*)d_in[6];
    const float* W2  = (const float*)d_in[7];
    const float* as2 = (const float*)d_in[8];
    const float* ad2 = (const float*)d_in[9];
    const float* b2  = (const float*)d_in[10];
    const float* f1w = (const float*)d_in[11];
    const float* f1b = (const float*)d_in[12];
    const float* f2w = (const float*)d_in[13];
    const float* f2b = (const float*)d_in[14];
    float* out = (float*)d_out;

    float *p_h1, *p_h2, *p_x2, *p_als1, *p_ald1, *p_als2, *p_ald2;
    bf16 *p_xh, *p_xl, *p_x1h, *p_x1l, *p_w1h, *p_w1l, *p_w2h, *p_w2l;
    cudaGetSymbolAddress((void**)&p_h1, g_h1);
    cudaGetSymbolAddress((void**)&p_h2, g_h2);
    cudaGetSymbolAddress((void**)&p_x2, g_x2);
    cudaGetSymbolAddress((void**)&p_xh, g_xh);
    cudaGetSymbolAddress((void**)&p_xl, g_xl);
    cudaGetSymbolAddress((void**)&p_x1h, g_x1h);
    cudaGetSymbolAddress((void**)&p_x1l, g_x1l);
    cudaGetSymbolAddress((void**)&p_w1h, g_w1h);
    cudaGetSymbolAddress((void**)&p_w1l, g_w1l);
    cudaGetSymbolAddress((void**)&p_w2h, g_w2h);
    cudaGetSymbolAddress((void**)&p_w2l, g_w2l);
    cudaGetSymbolAddress((void**)&p_als1, g_als1);
    cudaGetSymbolAddress((void**)&p_ald1, g_ald1);
    cudaGetSymbolAddress((void**)&p_als2, g_als2);
    cudaGetSymbolAddress((void**)&p_ald2, g_ald2);

    // graph prep + splits
    k_detect<<<1, 64>>>((const int*)ei);
    k_zero<<<(NN + 255) / 256, 256>>>();
    k_build<<<(ET + 255) / 256, 256>>>(ei);
    k_scan1<<<NB, 1024>>>();
    k_scan2<<<1, 32>>>();
    k_scan3<<<(NN + 255) / 256, 256>>>();
    k_scatter<<<(ET + 255) / 256, 256>>>();
    k_split<<<(NN * DD + 255) / 256, 256>>>(x, p_xh, p_xl, NN * DD);
    k_split<<<(DD * HD1 + 255) / 256, 256>>>(W1, p_w1h, p_w1l, DD * HD1);
    k_split<<<(HD1 * DD + 255) / 256, 256>>>(W2, p_w2h, p_w2l, HD1 * DD);

    // layer 1: h1 = x @ W1 (split-bf16 tensor cores)
    {
        dim3 grid(HD1 / 128, (NN + 127) / 128);
        k_mmagemm<<<grid, 256>>>(p_xh, p_xl, p_w1h, p_w1l, p_h1, NN, HD1, DD);
    }
    k_attdot<HH><<<NN, 32 * HH>>>(p_h1, as1, ad1, p_als1, p_ald1);
    k_gatagg<HH, 2, 0><<<NN, HH * 128>>>(p_h1, p_als1, p_ald1, b1, nullptr, p_x1h, p_x1l);

    // layer 2: h2 = x1 @ W2
    {
        dim3 grid(DD / 128, (NN + 127) / 128);
        k_mmagemm<<<grid, 256>>>(p_x1h, p_x1l, p_w2h, p_w2l, p_h2, NN, DD, HD1);
    }
    k_attdot<1><<<NN, 32>>>(p_h2, as2, ad2, p_als2, p_ald2);
    k_gatagg<1, 0, 1><<<NN, 128>>>(p_h2, p_als2, p_ald2, b2, p_x2, nullptr, nullptr);

    // pool + MLP
    k_pool<<<GG, 128>>>(bat, p_x2, f1w, f1b, f2w, f2b, out);
}

// round 4
// speedup vs baseline: 1.4597x; 1.0716x over previous
#include <cuda_runtime.h>
#include <cuda_bf16.h>
#include <cstdint>

#define NN 20000
#define EE 320000
#define ET (NN + EE)      // 340000 edges incl. self loops
#define DD 128
#define HH 4
#define HD1 (HH * DD)     // 512
#define GG 256
#define NB ((NN + 1023) / 1024)   // scan blocks (20)

typedef __nv_bfloat16 bf16;

// ---------------- scratch (static device globals; no allocs allowed) ----------
__device__ float g_h1[NN * HD1];
__device__ float g_x1[NN * HD1];
__device__ float g_h2[NN * DD];
__device__ float g_x2[NN * DD];
__device__ float g_als1[NN * HH];
__device__ float g_ald1[NN * HH];
__device__ float g_als2[NN];
__device__ float g_ald2[NN];
__device__ int   g_srcL[ET];
__device__ int   g_dstL[ET];
__device__ int   g_csrc[ET];
__device__ int   g_deg[NN];
__device__ int   g_cnt[NN];
__device__ int   g_rowptr[NN + 1];
__device__ int   g_bsum[32];
__device__ int   g_is64;

// ---------------- helpers ----------------
__device__ __forceinline__ float lrelu(float v) { return v > 0.f ? v : 0.2f * v; }

__device__ __forceinline__ int idx_get(const void* p, long long i) {
    if (g_is64) return (int)((const long long*)p)[i];
    return ((const int*)p)[i];
}

__device__ __forceinline__ void mma_bf16(float* c, const uint32_t* a, const uint32_t* b) {
    asm volatile(
        "mma.sync.aligned.m16n8k16.row.col.f32.bf16.bf16.f32 "
        "{%0,%1,%2,%3}, {%4,%5,%6,%7}, {%8,%9}, {%0,%1,%2,%3};\n"
        : "+f"(c[0]), "+f"(c[1]), "+f"(c[2]), "+f"(c[3])
        : "r"(a[0]), "r"(a[1]), "r"(a[2]), "r"(a[3]), "r"(b[0]), "r"(b[1]));
}
__device__ __forceinline__ void ldsm_x4(uint32_t* r, uint32_t addr) {
    asm volatile("ldmatrix.sync.aligned.m8n8.x4.shared.b16 {%0,%1,%2,%3}, [%4];"
                 : "=r"(r[0]), "=r"(r[1]), "=r"(r[2]), "=r"(r[3]) : "r"(addr));
}
__device__ __forceinline__ void ldsm_x4_t(uint32_t* r, uint32_t addr) {
    asm volatile("ldmatrix.sync.aligned.m8n8.x4.trans.shared.b16 {%0,%1,%2,%3}, [%4];"
                 : "=r"(r[0]), "=r"(r[1]), "=r"(r[2]), "=r"(r[3]) : "r"(addr));
}

// fp32x8 -> (hi bf16x8, lo bf16x8) in registers
__device__ __forceinline__ void split8(float4 u, float4 v, uint4& hi, uint4& lo) {
    float a[8] = {u.x, u.y, u.z, u.w, v.x, v.y, v.z, v.w};
    union { bf16 b[8]; uint4 q; } H, L;
#pragma unroll
    for (int i = 0; i < 8; i++) {
        bf16 h = __float2bfloat16(a[i]);
        H.b[i] = h;
        L.b[i] = __float2bfloat16(a[i] - __bfloat162float(h));
    }
    hi = H.q;
    lo = L.q;
}

// ---------------- graph prep ----------------
__global__ void k_detect(const int* ei) {
    __shared__ int s;
    if (threadIdx.x == 0) s = 0;
    __syncthreads();
    int v = ei[2 * threadIdx.x + 1];   // high words if int64 (all 0), random ids if int32
    if (v) atomicOr(&s, 1);
    __syncthreads();
    if (threadIdx.x == 0) g_is64 = (s == 0) ? 1 : 0;
}

__global__ void k_zero() {   // grid covers NN*HH
    int i = blockIdx.x * blockDim.x + threadIdx.x;
    if (i < NN) { g_deg[i] = 0; g_cnt[i] = 0; g_als2[i] = 0.f; g_ald2[i] = 0.f; }
    if (i < NN * HH) { g_als1[i] = 0.f; g_ald1[i] = 0.f; }
}

__global__ void k_build(const void* ei) {
    int i = blockIdx.x * blockDim.x + threadIdx.x;
    if (i >= ET) return;
    int s, d;
    if (i < EE) {
        s = idx_get(ei, i);
        d = idx_get(ei, (long long)EE + i);
    } else {
        s = d = i - EE;   // self loops
    }
    g_srcL[i] = s;
    g_dstL[i] = d;
    atomicAdd(&g_deg[d], 1);
}

// 3-kernel parallel exclusive scan of g_deg -> g_rowptr
__global__ void k_scan1() {
    int b = blockIdx.x, tid = threadIdx.x;
    int i = b * 1024 + tid;
    int v = (i < NN) ? g_deg[i] : 0;
    int lane = tid & 31, w = tid >> 5;
    int x = v;
#pragma unroll
    for (int o = 1; o < 32; o <<= 1) {
        int t = __shfl_up_sync(0xffffffffu, x, o);
        if (lane >= o) x += t;
    }
    __shared__ int ws[32];
    if (lane == 31) ws[w] = x;
    __syncthreads();
    if (w == 0) {
        int y = ws[lane];
#pragma unroll
        for (int o = 1; o < 32; o <<= 1) {
            int t = __shfl_up_sync(0xffffffffu, y, o);
            if (lane >= o) y += t;
        }
        ws[lane] = y;
    }
    __syncthreads();
    int incl = x + (w ? ws[w - 1] : 0);
    if (i < NN) g_rowptr[i + 1] = incl;
    if (tid == 1023) g_bsum[b] = incl;
}

__global__ void k_scan2() {
    int lane = threadIdx.x;
    int v = (lane < NB) ? g_bsum[lane] : 0;
    int x = v;
#pragma unroll
    for (int o = 1; o < 32; o <<= 1) {
        int t = __shfl_up_sync(0xffffffffu, x, o);
        if (lane >= o) x += t;
    }
    if (lane < 32) g_bsum[lane] = x - v;
}

__global__ void k_scan3() {
    int i = blockIdx.x * blockDim.x + threadIdx.x;
    if (i == 0) g_rowptr[0] = 0;
    if (i < NN) g_rowptr[i + 1] += g_bsum[i >> 10];
}

__global__ void k_scatter() {
    int i = blockIdx.x * blockDim.x + threadIdx.x;
    if (i >= ET) return;
    int d = g_dstL[i];
    int pos = g_rowptr[d] + atomicAdd(&g_cnt[d], 1);
    g_csrc[pos] = g_srcL[i];
}

// ---------------- split-bf16 TC GEMM + fused attention-dot epilogue ----------
// C = A@B with A,B fp32 (split to hi/lo bf16 in registers; Ah@Bh+Ah@Bl+Al@Bh).
// Epilogue also computes als[n,h] += sum_c C[n, h*128+c]*asrc[h,c] (and ald).
// Block: 128x128 tile, 256 thr, 8 warps (2Mx4N), warp 64x32, mma m16n8k16.
#define ASTR 24
#define BSTR 136

template <int H>
__global__ void __launch_bounds__(256, 2) k_mmagemm(
    const float* __restrict__ A, const float* __restrict__ B,
    float* __restrict__ C,
    const float* __restrict__ asrc, const float* __restrict__ adst,
    float* __restrict__ als, float* __restrict__ ald,
    int M, int Nc, int K) {
    __shared__ bf16 sA[2][2][128 * ASTR];
    __shared__ bf16 sB[2][2][16 * BSTR];
    int tid = threadIdx.x;
    int lane = tid & 31, w = tid >> 5;
    int warpM = (w >> 2) * 64, warpN = (w & 3) * 32;
    int rowBase = blockIdx.y * 128, colBase = blockIdx.x * 128;

    float acc[4][4][4];
#pragma unroll
    for (int a = 0; a < 4; a++)
#pragma unroll
        for (int b = 0; b < 4; b++)
#pragma unroll
            for (int c = 0; c < 4; c++) acc[a][b][c] = 0.f;

    int arow = rowBase + (tid >> 1);
    int akoff = (tid & 1) * 8;
    int brow = tid >> 4;
    int bcoff = (tid & 15) * 8;
    const float4 z4 = make_float4(0, 0, 0, 0);
    uint4 rah, ral, rbh, rbl;

#define GLOAD(k0)                                                                  \
    do {                                                                           \
        float4 a0f = z4, a1f = z4;                                                 \
        if (arow < M) {                                                            \
            a0f = *(const float4*)&A[(size_t)arow * K + (k0) + akoff];             \
            a1f = *(const float4*)&A[(size_t)arow * K + (k0) + akoff + 4];         \
        }                                                                          \
        split8(a0f, a1f, rah, ral);                                                \
        float4 b0f = *(const float4*)&B[(size_t)((k0) + brow) * Nc + colBase + bcoff];     \
        float4 b1f = *(const float4*)&B[(size_t)((k0) + brow) * Nc + colBase + bcoff + 4]; \
        split8(b0f, b1f, rbh, rbl);                                                \
    } while (0)

#define SSTORE(st)                                                                 \
    do {                                                                           \
        *(uint4*)&sA[st][0][(tid >> 1) * ASTR + akoff] = rah;                      \
        *(uint4*)&sA[st][1][(tid >> 1) * ASTR + akoff] = ral;                      \
        *(uint4*)&sB[st][0][brow * BSTR + bcoff] = rbh;                            \
        *(uint4*)&sB[st][1][brow * BSTR + bcoff] = rbl;                            \
    } while (0)

    GLOAD(0);
    SSTORE(0);
    __syncthreads();

    int KB = K / 16;
    int st = 0;
    for (int kb = 0; kb < KB; kb++) {
        if (kb + 1 < KB) GLOAD((kb + 1) * 16);

        uint32_t bh[4][2], bl[4][2];
#pragma unroll
        for (int g = 0; g < 2; g++) {
            uint32_t q[4];
            uint32_t addr = (uint32_t)__cvta_generic_to_shared(
                &sB[st][0][(lane & 15) * BSTR + warpN + g * 16 + (lane >> 4) * 8]);
            ldsm_x4_t(q, addr);
            bh[2 * g][0] = q[0]; bh[2 * g][1] = q[1];
            bh[2 * g + 1][0] = q[2]; bh[2 * g + 1][1] = q[3];
            addr = (uint32_t)__cvta_generic_to_shared(
                &sB[st][1][(lane & 15) * BSTR + warpN + g * 16 + (lane >> 4) * 8]);
            ldsm_x4_t(q, addr);
            bl[2 * g][0] = q[0]; bl[2 * g][1] = q[1];
            bl[2 * g + 1][0] = q[2]; bl[2 * g + 1][1] = q[3];
        }
#pragma unroll
        for (int mt = 0; mt < 4; mt++) {
            uint32_t ah[4], al[4];
            uint32_t addr = (uint32_t)__cvta_generic_to_shared(
                &sA[st][0][(warpM + mt * 16 + (lane & 15)) * ASTR + (lane >> 4) * 8]);
            ldsm_x4(ah, addr);
            addr = (uint32_t)__cvta_generic_to_shared(
                &sA[st][1][(warpM + mt * 16 + (lane & 15)) * ASTR + (lane >> 4) * 8]);
            ldsm_x4(al, addr);
#pragma unroll
            for (int nt = 0; nt < 4; nt++) {
                mma_bf16(acc[mt][nt], ah, bh[nt]);
                mma_bf16(acc[mt][nt], ah, bl[nt]);
                mma_bf16(acc[mt][nt], al, bh[nt]);
            }
        }
        if (kb + 1 < KB) {
            SSTORE(st ^ 1);
            st ^= 1;
            __syncthreads();
        }
    }
#undef GLOAD
#undef SSTORE

    // epilogue: C store + fused per-head dot products with asrc/adst
    int row0 = lane >> 2, col0 = (lane & 3) * 2;
    int head = (H > 1) ? (colBase >> 7) : 0;
    const float* as_h = asrc + head * DD;
    const float* ad_h = adst + head * DD;
#pragma unroll
    for (int mt = 0; mt < 4; mt++) {
        int r0 = rowBase + warpM + mt * 16 + row0;
        float s0 = 0.f, d0 = 0.f, s1 = 0.f, d1 = 0.f;
#pragma unroll
        for (int nt = 0; nt < 4; nt++) {
            int cc = warpN + nt * 8 + col0;
            float w0s = as_h[cc], w1s = as_h[cc + 1];
            float w0d = ad_h[cc], w1d = ad_h[cc + 1];
            if (r0 < M)
                *(float2*)&C[(size_t)r0 * Nc + colBase + cc] =
                    make_float2(acc[mt][nt][0], acc[mt][nt][1]);
            if (r0 + 8 < M)
                *(float2*)&C[(size_t)(r0 + 8) * Nc + colBase + cc] =
                    make_float2(acc[mt][nt][2], acc[mt][nt][3]);
            s0 += acc[mt][nt][0] * w0s + acc[mt][nt][1] * w1s;
            d0 += acc[mt][nt][0] * w0d + acc[mt][nt][1] * w1d;
            s1 += acc[mt][nt][2] * w0s + acc[mt][nt][3] * w1s;
            d1 += acc[mt][nt][2] * w0d + acc[mt][nt][3] * w1d;
        }
#pragma unroll
        for (int o = 1; o < 4; o <<= 1) {
            s0 += __shfl_xor_sync(0xffffffffu, s0, o);
            d0 += __shfl_xor_sync(0xffffffffu, d0, o);
            s1 += __shfl_xor_sync(0xffffffffu, s1, o);
            d1 += __shfl_xor_sync(0xffffffffu, d1, o);
        }
        if ((lane & 3) == 0) {
            if (r0 < M) { atomicAdd(&als[r0 * H + head], s0); atomicAdd(&ald[r0 * H + head], d0); }
            if (r0 + 8 < M) { atomicAdd(&als[(r0 + 8) * H + head], s1); atomicAdd(&ald[(r0 + 8) * H + head], d1); }
        }
    }
}

// ---------------- GAT aggregation: one block per dst node ----------------
// Softmax without max-subtraction (mathematically identical; logits are tiny).
// MODE 0: elu epilogue (layer 1). MODE 1: relu epilogue (layer 2).
template <int H, int LH, int MODE>
__global__ void __launch_bounds__(H * 128) k_gatagg(const float* __restrict__ hfeat,
                                                    const float* __restrict__ als,
                                                    const float* __restrict__ ald,
                                                    const float* __restrict__ bias,
                                                    float* __restrict__ outf) {
    const int HDx = H * 128;
    int d = blockIdx.x;
    int tid = threadIdx.x;
    int h = tid >> 7;
    int beg = g_rowptr[d], end = g_rowptr[d + 1];
    int deg = end - beg;

    __shared__ float sden[H], sinv[H], sald[H];
    __shared__ float sal[64 * H];
    __shared__ int ssrc[64];
    if (tid < H) { sden[tid] = 0.f; sald[tid] = ald[d * H + tid]; }
    __syncthreads();

    for (int i = tid; i < deg * H; i += HDx) {
        int e = i >> LH, hh = i & (H - 1);
        int s = g_csrc[beg + e];
        float ev = lrelu(als[s * H + hh] + sald[hh]);
        atomicAdd(&sden[hh], __expf(ev));
    }
    __syncthreads();
    if (tid < H) sinv[tid] = 1.f / sden[tid];
    __syncthreads();

    float acc0 = 0.f, acc1 = 0.f, acc2 = 0.f, acc3 = 0.f;
    for (int cb = beg; cb < end; cb += 64) {
        int cn = min(64, end - cb);
        if (tid < cn) ssrc[tid] = g_csrc[cb + tid];
        __syncthreads();
        for (int i = tid; i < cn * H; i += HDx) {
            int e = i >> LH, hh = i & (H - 1);
            float ev = lrelu(als[ssrc[e] * H + hh] + sald[hh]);
            sal[i] = __expf(ev) * sinv[hh];
        }
        __syncthreads();
        int j = 0;
        for (; j + 8 <= cn; j += 8) {
            const float* r0 = hfeat + (size_t)ssrc[j + 0] * HDx;
            const float* r1 = hfeat + (size_t)ssrc[j + 1] * HDx;
            const float* r2 = hfeat + (size_t)ssrc[j + 2] * HDx;
            const float* r3 = hfeat + (size_t)ssrc[j + 3] * HDx;
            const float* r4 = hfeat + (size_t)ssrc[j + 4] * HDx;
            const float* r5 = hfeat + (size_t)ssrc[j + 5] * HDx;
            const float* r6 = hfeat + (size_t)ssrc[j + 6] * HDx;
            const float* r7 = hfeat + (size_t)ssrc[j + 7] * HDx;
            acc0 += sal[(j + 0) * H + h] * r0[tid];
            acc1 += sal[(j + 1) * H + h] * r1[tid];
            acc2 += sal[(j + 2) * H + h] * r2[tid];
            acc3 += sal[(j + 3) * H + h] * r3[tid];
            acc0 += sal[(j + 4) * H + h] * r4[tid];
            acc1 += sal[(j + 5) * H + h] * r5[tid];
            acc2 += sal[(j + 6) * H + h] * r6[tid];
            acc3 += sal[(j + 7) * H + h] * r7[tid];
        }
        for (; j < cn; j++)
            acc0 += sal[j * H + h] * hfeat[(size_t)ssrc[j] * HDx + tid];
        __syncthreads();
    }

    float v = (acc0 + acc1) + (acc2 + acc3) + bias[tid];
    v = MODE ? fmaxf(v, 0.f) : (v > 0.f ? v : expm1f(v));
    outf[(size_t)d * HDx + tid] = v;
}

// ---------------- fused global-max-pool + MLP ----------------
__global__ void k_pool(const void* batch, const float* __restrict__ x2,
                       const float* __restrict__ f1w, const float* __restrict__ f1b,
                       const float* __restrict__ f2w, const float* __restrict__ f2b,
                       float* __restrict__ out) {
    int g = blockIdx.x;
    int tid = threadIdx.x;  // 128
    __shared__ int slo, shi;
    if (tid == 0) {
        int lo = 0, hi = NN;
        while (lo < hi) { int mid = (lo + hi) >> 1; if (idx_get(batch, mid) < g) lo = mid + 1; else hi = mid; }
        slo = lo;
        lo = 0; hi = NN;
        while (lo < hi) { int mid = (lo + hi) >> 1; if (idx_get(batch, mid) < g + 1) lo = mid + 1; else hi = mid; }
        shi = lo;
    }
    __syncthreads();
    __shared__ float pr[128];
    float m = 0.f;
    for (int n = slo; n < shi; n++) m = fmaxf(m, x2[(size_t)n * 128 + tid]);
    pr[tid] = m;
    __syncthreads();
    __shared__ float hb[16];
    if (tid < 16) {
        float s = f1b[tid];
        for (int c = 0; c < 128; c++) s += pr[c] * f1w[c * 16 + tid];
        hb[tid] = fmaxf(s, 0.f);
    }
    __syncthreads();
    if (tid == 0) {
        float s = f2b[0];
        for (int j = 0; j < 16; j++) s += hb[j] * f2w[j];
        out[g] = s;
    }
}

// ---------------- launch ----------------
extern "C" void kernel_launch(void* const* d_in, const int* in_sizes, int n_in,
                              void* d_out, int out_size) {
    const float* x   = (const float*)d_in[0];
    const void*  ei  = d_in[1];
    const void*  bat = d_in[2];
    const float* W1  = (const float*)d_in[3];
    const float* as1 = (const float*)d_in[4];
    const float* ad1 = (const float*)d_in[5];
    const float* b1  = (const float*)d_in[6];
    const float* W2  = (const float*)d_in[7];
    const float* as2 = (const float*)d_in[8];
    const float* ad2 = (const float*)d_in[9];
    const float* b2  = (const float*)d_in[10];
    const float* f1w = (const float*)d_in[11];
    const float* f1b = (const float*)d_in[12];
    const float* f2w = (const float*)d_in[13];
    const float* f2b = (const float*)d_in[14];
    float* out = (float*)d_out;

    float *p_h1, *p_x1, *p_h2, *p_x2, *p_als1, *p_ald1, *p_als2, *p_ald2;
    cudaGetSymbolAddress((void**)&p_h1, g_h1);
    cudaGetSymbolAddress((void**)&p_x1, g_x1);
    cudaGetSymbolAddress((void**)&p_h2, g_h2);
    cudaGetSymbolAddress((void**)&p_x2, g_x2);
    cudaGetSymbolAddress((void**)&p_als1, g_als1);
    cudaGetSymbolAddress((void**)&p_ald1, g_ald1);
    cudaGetSymbolAddress((void**)&p_als2, g_als2);
    cudaGetSymbolAddress((void**)&p_ald2, g_ald2);

    // graph prep
    k_detect<<<1, 64>>>((const int*)ei);
    k_zero<<<(NN * HH + 255) / 256, 256>>>();
    k_build<<<(ET + 255) / 256, 256>>>(ei);
    k_scan1<<<NB, 1024>>>();
    k_scan2<<<1, 32>>>();
    k_scan3<<<(NN + 255) / 256, 256>>>();
    k_scatter<<<(ET + 255) / 256, 256>>>();

    // layer 1: h1 = x @ W1 (on-the-fly split-bf16 TC GEMM + fused attdot)
    {
        dim3 grid(HD1 / 128, (NN + 127) / 128);
        k_mmagemm<HH><<<grid, 256>>>(x, W1, p_h1, as1, ad1, p_als1, p_ald1, NN, HD1, DD);
    }
    k_gatagg<HH, 2, 0><<<NN, HH * 128>>>(p_h1, p_als1, p_ald1, b1, p_x1);

    // layer 2: h2 = x1 @ W2
    {
        dim3 grid(DD / 128, (NN + 127) / 128);
        k_mmagemm<1><<<grid, 256>>>(p_x1, W2, p_h2, as2, ad2, p_als2, p_ald2, NN, DD, HD1);
    }
    k_gatagg<1, 0, 1><<<NN, 128>>>(p_h2, p_als2, p_ald2, b2, p_x2);

    // pool + MLP
    k_pool<<<GG, 128>>>(bat, p_x2, f1w, f1b, f2w, f2b, out);
}